// round 6
// baseline (speedup 1.0000x reference)
#include <cuda_runtime.h>

// Problem shape (fixed by the reference)
#define S 32768
#define H 1024
#define B1 444           // blocks = 3 per SM on 148 SMs (all co-resident -> grid barrier safe)
#define TPB 256
#define WPB 8            // warps per block
#define NF4 (H / 4)      // 256 float4 columns

// Transposed partial layout: g_part[f4col][block] -> contiguous per column in phase 2.
__device__ float4 g_part[NF4][B1];
// Monotone arrival counter (zero at module load; epoch trick => no reset, graph-replay safe).
__device__ unsigned int g_cnt;

__global__ __launch_bounds__(TPB, 3)
void cosattn_fused(const float* __restrict__ query,
                   const float* __restrict__ keys,
                   float* __restrict__ out) {
    __shared__ float q_s[H];             // 4 KB: query lives here, not in regs
    __shared__ float warp_ctx[WPB][H];   // 32 KB: block reduce / phase-2 buffer

    const int tid  = threadIdx.x;
    const int wid  = tid >> 5;
    const int lane = tid & 31;
    const int gwarp  = blockIdx.x * WPB + wid;
    const int nwarps = B1 * WPB;

    // Stage query into smem.
    for (int i = tid; i < NF4; i += TPB)
        ((float4*)q_s)[i] = ((const float4*)query)[i];
    __syncthreads();

    // Per-warp |q| from smem (one-time, cheap).
    const float4* qs4 = (const float4*)q_s;
    float qss = 0.f;
#pragma unroll
    for (int j = 0; j < 8; j++) {
        float4 q = qs4[lane + 32 * j];
        qss += q.x * q.x + q.y * q.y + q.z * q.z + q.w * q.w;
    }
#pragma unroll
    for (int o = 16; o > 0; o >>= 1)
        qss += __shfl_xor_sync(0xffffffffu, qss, o);
    const float qn_inv = rsqrtf(qss);

    float4 acc[8];
#pragma unroll
    for (int j = 0; j < 8; j++) acc[j] = make_float4(0.f, 0.f, 0.f, 0.f);

    for (int row = gwarp; row < S; row += nwarps) {
        const float4* k4 = (const float4*)(keys + (size_t)row * H);

        // Pass 1: dot & sum-of-squares; kv streamed in two 4-float4 batches (16 regs).
        float dot = 0.f, ss = 0.f;
#pragma unroll
        for (int b = 0; b < 2; b++) {
            float4 kv[4];
#pragma unroll
            for (int j = 0; j < 4; j++) kv[j] = k4[lane + 32 * (4 * b + j)];
#pragma unroll
            for (int j = 0; j < 4; j++) {
                float4 q = qs4[lane + 32 * (4 * b + j)];
                dot += q.x * kv[j].x + q.y * kv[j].y + q.z * kv[j].z + q.w * kv[j].w;
                ss  += kv[j].x * kv[j].x + kv[j].y * kv[j].y
                     + kv[j].z * kv[j].z + kv[j].w * kv[j].w;
            }
        }

        // Pass 2 loads are independent of the shuffles: issue them first so the
        // L1 re-reads overlap the butterfly latency.
        float4 rv[8];
#pragma unroll
        for (int j = 0; j < 8; j++) rv[j] = k4[lane + 32 * j];   // L1-hot

        // Interleaved butterflies (independent chains overlap).
#pragma unroll
        for (int o = 16; o > 0; o >>= 1) {
            dot += __shfl_xor_sync(0xffffffffu, dot, o);
            ss  += __shfl_xor_sync(0xffffffffu, ss, o);
        }
        const float cosv = dot * qn_inv * rsqrtf(ss);

#pragma unroll
        for (int j = 0; j < 8; j++) {
            acc[j].x += cosv * rv[j].x;
            acc[j].y += cosv * rv[j].y;
            acc[j].z += cosv * rv[j].z;
            acc[j].w += cosv * rv[j].w;
        }
    }

    // Block-level reduce: per-warp slice to shared, thread tid sums its float4 column.
    float4* wctx4 = (float4*)warp_ctx[wid];
#pragma unroll
    for (int j = 0; j < 8; j++) wctx4[lane + 32 * j] = acc[j];
    __syncthreads();

    float4 sum = make_float4(0.f, 0.f, 0.f, 0.f);
#pragma unroll
    for (int w = 0; w < WPB; w++) {
        float4 v = ((const float4*)warp_ctx[w])[tid];
        sum.x += v.x; sum.y += v.y; sum.z += v.z; sum.w += v.w;
    }
    g_part[tid][blockIdx.x] = sum;   // transposed store (256 scattered float4 per block)

    // ---------------- Grid barrier (all 444 blocks co-resident) ----------------
    __threadfence();
    __syncthreads();
    if (tid == 0) {
        unsigned int old = atomicAdd(&g_cnt, 1u);
        unsigned int target = old - (old % B1) + B1;   // next multiple of B1 (epoch-safe)
        while (*(volatile unsigned int*)&g_cnt < target)
            __nanosleep(64);
    }
    __syncthreads();
    __threadfence();

    // ---------------- Phase 2: cross-block reduction ----------------
    const int b = blockIdx.x;
    if (b < NF4) {
        float4 a = make_float4(0.f, 0.f, 0.f, 0.f);
        for (int r = tid; r < B1; r += TPB) {          // coalesced contiguous float4
            float4 v = g_part[b][r];
            a.x += v.x; a.y += v.y; a.z += v.z; a.w += v.w;
        }
        float4* red = (float4*)warp_ctx[0];
        red[tid] = a;
        __syncthreads();
#pragma unroll
        for (int s = TPB / 2; s > 0; s >>= 1) {
            if (tid < s) {
                float4 o = red[tid + s];
                red[tid].x += o.x; red[tid].y += o.y;
                red[tid].z += o.z; red[tid].w += o.w;
            }
            __syncthreads();
        }
        if (tid == 0)
            ((float4*)out)[b] = red[0];
    }
}

extern "C" void kernel_launch(void* const* d_in, const int* in_sizes, int n_in,
                              void* d_out, int out_size) {
    const float* query = (const float*)d_in[0];  // [1, 1024]
    const float* keys  = (const float*)d_in[1];  // [32768, 1024]
    float* out = (float*)d_out;                  // [1, 1024]

    cosattn_fused<<<B1, TPB>>>(query, keys, out);
}

// round 7
// speedup vs baseline: 1.0780x; 1.0780x over previous
#include <cuda_runtime.h>

// Problem shape (fixed by the reference)
#define S 32768
#define H 1024
#define B1 296           // 2 blocks per SM on 148 SMs (co-resident -> grid barrier safe)
#define TPB 256
#define WPB 8
#define NF4 (H / 4)
#define NWARPS (B1 * WPB)   // 2368

// Transposed partials: g_part[f4col][block] -> contiguous per column in phase 2.
__device__ float4 g_part[NF4][B1];
__device__ unsigned int g_cnt;   // monotone epoch counter (graph-replay safe)

struct Acc8 { float4 v[8]; };

__device__ __forceinline__ void load_row(float4 kv[8], const float* __restrict__ keys,
                                         int row, int lane) {
    const float4* k4 = (const float4*)(keys + (size_t)row * H);
#pragma unroll
    for (int j = 0; j < 8; j++) kv[j] = k4[lane + 32 * j];
}

__device__ __forceinline__ void process_row(const float4 kv[8], const float4* qs4,
                                            float qn_inv, int lane, Acc8& acc) {
    float dot = 0.f, ss = 0.f;
#pragma unroll
    for (int j = 0; j < 8; j++) {
        float4 q = qs4[lane + 32 * j];
        dot += q.x * kv[j].x + q.y * kv[j].y + q.z * kv[j].z + q.w * kv[j].w;
        ss  += kv[j].x * kv[j].x + kv[j].y * kv[j].y
             + kv[j].z * kv[j].z + kv[j].w * kv[j].w;
    }
#pragma unroll
    for (int o = 16; o > 0; o >>= 1) {
        dot += __shfl_xor_sync(0xffffffffu, dot, o);
        ss  += __shfl_xor_sync(0xffffffffu, ss, o);
    }
    const float cosv = dot * qn_inv * rsqrtf(ss);
#pragma unroll
    for (int j = 0; j < 8; j++) {
        acc.v[j].x += cosv * kv[j].x;
        acc.v[j].y += cosv * kv[j].y;
        acc.v[j].z += cosv * kv[j].z;
        acc.v[j].w += cosv * kv[j].w;
    }
}

__global__ __launch_bounds__(TPB, 2)
void cosattn_fused(const float* __restrict__ query,
                   const float* __restrict__ keys,
                   float* __restrict__ out) {
    __shared__ float q_s[H];             // 4 KB
    __shared__ float warp_ctx[WPB][H];   // 32 KB

    const int tid  = threadIdx.x;
    const int wid  = tid >> 5;
    const int lane = tid & 31;
    const int gwarp = blockIdx.x * WPB + wid;

    for (int i = tid; i < NF4; i += TPB)
        ((float4*)q_s)[i] = ((const float4*)query)[i];
    __syncthreads();

    const float4* qs4 = (const float4*)q_s;
    float qss = 0.f;
#pragma unroll
    for (int j = 0; j < 8; j++) {
        float4 q = qs4[lane + 32 * j];
        qss += q.x * q.x + q.y * q.y + q.z * q.z + q.w * q.w;
    }
#pragma unroll
    for (int o = 16; o > 0; o >>= 1)
        qss += __shfl_xor_sync(0xffffffffu, qss, o);
    const float qn_inv = rsqrtf(qss);

    Acc8 acc;
#pragma unroll
    for (int j = 0; j < 8; j++) acc.v[j] = make_float4(0.f, 0.f, 0.f, 0.f);

    // ---- Software-pipelined main loop: prefetch row n+1 before processing row n ----
    float4 ka[8], kb[8];
    int row = gwarp;                       // gwarp < 2368 < S always
    load_row(ka, keys, row, lane);
    for (;;) {
        int r1 = row + NWARPS;
        if (r1 < S) load_row(kb, keys, r1, lane);   // LDGs issue before ka's compute
        process_row(ka, qs4, qn_inv, lane, acc);
        if (r1 >= S) break;

        int r2 = r1 + NWARPS;
        if (r2 < S) load_row(ka, keys, r2, lane);
        process_row(kb, qs4, qn_inv, lane, acc);
        if (r2 >= S) break;
        row = r2;
    }

    // Block-level reduce via smem.
    float4* wctx4 = (float4*)warp_ctx[wid];
#pragma unroll
    for (int j = 0; j < 8; j++) wctx4[lane + 32 * j] = acc.v[j];
    __syncthreads();

    float4 sum = make_float4(0.f, 0.f, 0.f, 0.f);
#pragma unroll
    for (int w = 0; w < WPB; w++) {
        float4 v = ((const float4*)warp_ctx[w])[tid];
        sum.x += v.x; sum.y += v.y; sum.z += v.z; sum.w += v.w;
    }
    g_part[tid][blockIdx.x] = sum;

    // ---- Grid barrier (296 co-resident blocks) ----
    __threadfence();
    __syncthreads();
    if (tid == 0) {
        unsigned int old = atomicAdd(&g_cnt, 1u);
        unsigned int target = old - (old % B1) + B1;
        while (*(volatile unsigned int*)&g_cnt < target)
            __nanosleep(64);
    }
    __syncthreads();
    __threadfence();

    // ---- Phase 2: cross-block reduction ----
    const int b = blockIdx.x;
    if (b < NF4) {
        float4 a = make_float4(0.f, 0.f, 0.f, 0.f);
        for (int r = tid; r < B1; r += TPB) {
            float4 v = g_part[b][r];
            a.x += v.x; a.y += v.y; a.z += v.z; a.w += v.w;
        }
        float4* red = (float4*)warp_ctx[0];
        red[tid] = a;
        __syncthreads();
#pragma unroll
        for (int s = TPB / 2; s > 0; s >>= 1) {
            if (tid < s) {
                float4 o = red[tid + s];
                red[tid].x += o.x; red[tid].y += o.y;
                red[tid].z += o.z; red[tid].w += o.w;
            }
            __syncthreads();
        }
        if (tid == 0)
            ((float4*)out)[b] = red[0];
    }
}

extern "C" void kernel_launch(void* const* d_in, const int* in_sizes, int n_in,
                              void* d_out, int out_size) {
    const float* query = (const float*)d_in[0];  // [1, 1024]
    const float* keys  = (const float*)d_in[1];  // [32768, 1024]
    float* out = (float*)d_out;                  // [1, 1024]

    cosattn_fused<<<B1, TPB>>>(query, keys, out);
}

// round 9
// speedup vs baseline: 1.1212x; 1.0401x over previous
#include <cuda_runtime.h>
#include <cstdint>

// Problem shape (fixed by the reference)
#define S 32768
#define H 1024
#define B1 444            // 3 CTAs/SM x 148 SMs, guaranteed by launch_bounds + 68KB smem
#define TPB 256
#define WPB 8
#define NF4 (H / 4)
#define NWARPS (B1 * WPB) // 3552

// Dynamic smem layout: q_s[1024] | stage[8 warps][2 bufs][1024]
#define SMEM_FLOATS (H + WPB * 2 * H)
#define SMEM_BYTES (SMEM_FLOATS * 4)   // 69632 B

// Transposed partials: g_part[f4col][block] -> contiguous per column in phase 2.
__device__ float4 g_part[NF4][B1];
__device__ unsigned int g_cnt;   // monotone epoch counter (graph-replay safe)

extern __shared__ float smem_dyn[];

__device__ __forceinline__ void cp16(uint32_t dst, const float* src) {
    asm volatile("cp.async.cg.shared.global [%0], [%1], 16;" :: "r"(dst), "l"(src));
}
__device__ __forceinline__ void cp_commit() { asm volatile("cp.async.commit_group;"); }
__device__ __forceinline__ void cp_wait1()  { asm volatile("cp.async.wait_group 1;"); }
__device__ __forceinline__ void cp_wait0()  { asm volatile("cp.async.wait_group 0;"); }

__global__ __launch_bounds__(TPB, 3)
void cosattn_fused(const float* __restrict__ query,
                   const float* __restrict__ keys,
                   float* __restrict__ out) {
    float* q_s   = smem_dyn;        // H floats
    float* stage = smem_dyn + H;    // WPB*2*H floats

    const int tid  = threadIdx.x;
    const int wid  = tid >> 5;
    const int lane = tid & 31;
    const int gwarp = blockIdx.x * WPB + wid;   // < 3552 < S always

    // Stage query.
    for (int i = tid; i < NF4; i += TPB)
        ((float4*)q_s)[i] = ((const float4*)query)[i];
    __syncthreads();

    const float4* qs4 = (const float4*)q_s;
    float qss = 0.f;
#pragma unroll
    for (int j = 0; j < 8; j++) {
        float4 q = qs4[lane + 32 * j];
        qss += q.x * q.x + q.y * q.y + q.z * q.z + q.w * q.w;
    }
#pragma unroll
    for (int o = 16; o > 0; o >>= 1)
        qss += __shfl_xor_sync(0xffffffffu, qss, o);
    const float qn_inv = rsqrtf(qss);

    float4 acc[8];
#pragma unroll
    for (int j = 0; j < 8; j++) acc[j] = make_float4(0.f, 0.f, 0.f, 0.f);

    // Per-warp private 2-deep cp.async row pipeline.
    float* my_stage = stage + wid * (2 * H);
    const uint32_t st_u32 = (uint32_t)__cvta_generic_to_shared(my_stage);
    const int nit = (S - 1 - gwarp) / NWARPS + 1;   // rows this warp owns (>=1)

    // Prologue: prefetch rows it=0,1 (guarded; empty commits keep group count aligned).
    {
        const float* src0 = keys + (size_t)gwarp * H;
#pragma unroll
        for (int j = 0; j < 8; j++)
            cp16(st_u32 + (uint32_t)(lane + 32 * j) * 16u,
                 src0 + (lane + 32 * j) * 4);
    }
    cp_commit();
    if (1 < nit) {
        const float* src1 = keys + (size_t)(gwarp + NWARPS) * H;
#pragma unroll
        for (int j = 0; j < 8; j++)
            cp16(st_u32 + (uint32_t)(H * 4) + (uint32_t)(lane + 32 * j) * 16u,
                 src1 + (lane + 32 * j) * 4);
    }
    cp_commit();

    for (int it = 0; it < nit; it++) {
        cp_wait1();   // group 'it' complete
        const float4* row4 = (const float4*)(my_stage + (it & 1) * H);

        float dot = 0.f, ss = 0.f;
#pragma unroll
        for (int j = 0; j < 8; j++) {
            float4 k = row4[lane + 32 * j];
            float4 q = qs4[lane + 32 * j];
            dot += q.x * k.x + q.y * k.y + q.z * k.z + q.w * k.w;
            ss  += k.x * k.x + k.y * k.y + k.z * k.z + k.w * k.w;
        }
#pragma unroll
        for (int o = 16; o > 0; o >>= 1) {
            dot += __shfl_xor_sync(0xffffffffu, dot, o);
            ss  += __shfl_xor_sync(0xffffffffu, ss, o);
        }
        const float cosv = dot * qn_inv * rsqrtf(ss);

#pragma unroll
        for (int j = 0; j < 8; j++) {
            float4 k = row4[lane + 32 * j];
            acc[j].x += cosv * k.x;
            acc[j].y += cosv * k.y;
            acc[j].z += cosv * k.z;
            acc[j].w += cosv * k.w;
        }

        // Refill the buffer just consumed with row it+2.
        if (it + 2 < nit) {
            const float* src = keys + (size_t)(gwarp + (size_t)(it + 2) * NWARPS) * H;
            const uint32_t dst = st_u32 + (uint32_t)((it & 1) * H * 4);
#pragma unroll
            for (int j = 0; j < 8; j++)
                cp16(dst + (uint32_t)(lane + 32 * j) * 16u, src + (lane + 32 * j) * 4);
        }
        cp_commit();
    }
    cp_wait0();
    __syncthreads();

    // Block-level reduce: reuse stage area as ctx[WPB][H].
    float* ctx = stage;
    float4* w4 = (float4*)(ctx + wid * H);
#pragma unroll
    for (int j = 0; j < 8; j++) w4[lane + 32 * j] = acc[j];
    __syncthreads();

    float4 sum = make_float4(0.f, 0.f, 0.f, 0.f);
#pragma unroll
    for (int w = 0; w < WPB; w++) {
        float4 v = ((const float4*)(ctx + w * H))[tid];
        sum.x += v.x; sum.y += v.y; sum.z += v.z; sum.w += v.w;
    }
    g_part[tid][blockIdx.x] = sum;

    // ---- Grid barrier (444 co-resident blocks, guaranteed by launch_bounds(256,3)) ----
    __threadfence();
    __syncthreads();
    if (tid == 0) {
        unsigned int old = atomicAdd(&g_cnt, 1u);
        unsigned int target = old - (old % B1) + B1;
        while (*(volatile unsigned int*)&g_cnt < target)
            __nanosleep(64);
    }
    __syncthreads();
    __threadfence();

    // ---- Phase 2: cross-block reduction (blocks 0..255; red buffer reuses q_s) ----
    const int b = blockIdx.x;
    if (b < NF4) {
        float4 a = make_float4(0.f, 0.f, 0.f, 0.f);
        for (int r = tid; r < B1; r += TPB) {
            float4 v = g_part[b][r];
            a.x += v.x; a.y += v.y; a.z += v.z; a.w += v.w;
        }
        float4* red = (float4*)q_s;
        red[tid] = a;
        __syncthreads();
#pragma unroll
        for (int s = TPB / 2; s > 0; s >>= 1) {
            if (tid < s) {
                float4 o = red[tid + s];
                red[tid].x += o.x; red[tid].y += o.y;
                red[tid].z += o.z; red[tid].w += o.w;
            }
            __syncthreads();
        }
        if (tid == 0)
            ((float4*)out)[b] = red[0];
    }
}

extern "C" void kernel_launch(void* const* d_in, const int* in_sizes, int n_in,
                              void* d_out, int out_size) {
    const float* query = (const float*)d_in[0];  // [1, 1024]
    const float* keys  = (const float*)d_in[1];  // [32768, 1024]
    float* out = (float*)d_out;                  // [1, 1024]

    cudaFuncSetAttribute(cosattn_fused,
                         cudaFuncAttributeMaxDynamicSharedMemorySize, SMEM_BYTES);
    cosattn_fused<<<B1, TPB, SMEM_BYTES>>>(query, keys, out);
}

// round 10
// speedup vs baseline: 1.1531x; 1.0285x over previous
#include <cuda_runtime.h>

// Problem shape (fixed by the reference)
#define S 32768
#define H 1024
#define B1 296            // 2 CTAs/SM x 148 SMs (co-resident -> grid barrier safe)
#define TPB 256
#define WPB 8
#define NF4 (H / 4)
#define NWARPS (B1 * WPB) // 2368

// Transposed partials: g_part[f4col][block] -> contiguous per column in phase 2.
__device__ float4 g_part[NF4][B1];
__device__ unsigned int g_cnt;   // monotone epoch counter (graph-replay safe)

__global__ __launch_bounds__(TPB, 2)
void cosattn_fused(const float* __restrict__ query,
                   const float* __restrict__ keys,
                   float* __restrict__ out) {
    __shared__ float q_s[H];             // 4 KB
    __shared__ float warp_ctx[WPB][H];   // 32 KB

    const int tid  = threadIdx.x;
    const int wid  = tid >> 5;
    const int lane = tid & 31;
    const int gwarp = blockIdx.x * WPB + wid;   // < 2368

    for (int i = tid; i < NF4; i += TPB)
        ((float4*)q_s)[i] = ((const float4*)query)[i];
    __syncthreads();

    const float4* qs4 = (const float4*)q_s;
    float qss = 0.f;
#pragma unroll
    for (int j = 0; j < 8; j++) {
        float4 q = qs4[lane + 32 * j];
        qss += q.x * q.x + q.y * q.y + q.z * q.z + q.w * q.w;
    }
#pragma unroll
    for (int o = 16; o > 0; o >>= 1)
        qss += __shfl_xor_sync(0xffffffffu, qss, o);
    const float qn_inv = rsqrtf(qss);

    float4 acc[8];
#pragma unroll
    for (int j = 0; j < 8; j++) acc[j] = make_float4(0.f, 0.f, 0.f, 0.f);

    // ---- Main loop: 2 rows per iteration, one interleaved butterfly ----
    for (int r = gwarp; r < S; r += 2 * NWARPS) {
        const int rB = r + NWARPS;
        const bool hasB = (rB < S);

        const float4* kA4 = (const float4*)(keys + (size_t)r * H);
        const float4* kB4 = (const float4*)(keys + (size_t)(hasB ? rB : r) * H);

        // Front-batched loads for both rows (16 LDG.128 in flight).
        float4 kvA[8], kvB[8];
#pragma unroll
        for (int j = 0; j < 8; j++) kvA[j] = kA4[lane + 32 * j];
#pragma unroll
        for (int j = 0; j < 8; j++) kvB[j] = kB4[lane + 32 * j];

        float dotA = 0.f, ssA = 0.f, dotB = 0.f, ssB = 0.f;
#pragma unroll
        for (int j = 0; j < 8; j++) {
            float4 q = qs4[lane + 32 * j];
            dotA += q.x * kvA[j].x + q.y * kvA[j].y + q.z * kvA[j].z + q.w * kvA[j].w;
            ssA  += kvA[j].x * kvA[j].x + kvA[j].y * kvA[j].y
                  + kvA[j].z * kvA[j].z + kvA[j].w * kvA[j].w;
            dotB += q.x * kvB[j].x + q.y * kvB[j].y + q.z * kvB[j].z + q.w * kvB[j].w;
            ssB  += kvB[j].x * kvB[j].x + kvB[j].y * kvB[j].y
                  + kvB[j].z * kvB[j].z + kvB[j].w * kvB[j].w;
        }

        // One butterfly, 4 independent chains interleaved (overlapping SHFL latency).
#pragma unroll
        for (int o = 16; o > 0; o >>= 1) {
            dotA += __shfl_xor_sync(0xffffffffu, dotA, o);
            ssA  += __shfl_xor_sync(0xffffffffu, ssA, o);
            dotB += __shfl_xor_sync(0xffffffffu, dotB, o);
            ssB  += __shfl_xor_sync(0xffffffffu, ssB, o);
        }

        const float cosA = dotA * qn_inv * rsqrtf(ssA);
        const float cosB = hasB ? (dotB * qn_inv * rsqrtf(ssB)) : 0.f;

#pragma unroll
        for (int j = 0; j < 8; j++) {
            acc[j].x += cosA * kvA[j].x + cosB * kvB[j].x;
            acc[j].y += cosA * kvA[j].y + cosB * kvB[j].y;
            acc[j].z += cosA * kvA[j].z + cosB * kvB[j].z;
            acc[j].w += cosA * kvA[j].w + cosB * kvB[j].w;
        }
    }

    // Block-level reduce via smem.
    float4* wctx4 = (float4*)warp_ctx[wid];
#pragma unroll
    for (int j = 0; j < 8; j++) wctx4[lane + 32 * j] = acc[j];
    __syncthreads();

    float4 sum = make_float4(0.f, 0.f, 0.f, 0.f);
#pragma unroll
    for (int w = 0; w < WPB; w++) {
        float4 v = ((const float4*)warp_ctx[w])[tid];
        sum.x += v.x; sum.y += v.y; sum.z += v.z; sum.w += v.w;
    }
    g_part[tid][blockIdx.x] = sum;

    // ---- Grid barrier (296 co-resident blocks) ----
    __threadfence();
    __syncthreads();
    if (tid == 0) {
        unsigned int old = atomicAdd(&g_cnt, 1u);
        unsigned int target = old - (old % B1) + B1;
        while (*(volatile unsigned int*)&g_cnt < target)
            __nanosleep(64);
    }
    __syncthreads();
    __threadfence();

    // ---- Phase 2: cross-block reduction ----
    const int b = blockIdx.x;
    if (b < NF4) {
        float4 a = make_float4(0.f, 0.f, 0.f, 0.f);
        for (int r = tid; r < B1; r += TPB) {
            float4 v = g_part[b][r];
            a.x += v.x; a.y += v.y; a.z += v.z; a.w += v.w;
        }
        float4* red = (float4*)warp_ctx[0];
        red[tid] = a;
        __syncthreads();
#pragma unroll
        for (int s = TPB / 2; s > 0; s >>= 1) {
            if (tid < s) {
                float4 o = red[tid + s];
                red[tid].x += o.x; red[tid].y += o.y;
                red[tid].z += o.z; red[tid].w += o.w;
            }
            __syncthreads();
        }
        if (tid == 0)
            ((float4*)out)[b] = red[0];
    }
}

extern "C" void kernel_launch(void* const* d_in, const int* in_sizes, int n_in,
                              void* d_out, int out_size) {
    const float* query = (const float*)d_in[0];  // [1, 1024]
    const float* keys  = (const float*)d_in[1];  // [32768, 1024]
    float* out = (float*)d_out;                  // [1, 1024]

    cosattn_fused<<<B1, TPB>>>(query, keys, out);
}

// round 11
// speedup vs baseline: 1.2278x; 1.0648x over previous
#include <cuda_runtime.h>

// Problem shape (fixed by the reference)
#define S 32768
#define H 1024
#define B1 148            // 1 CTA per SM (co-resident -> grid barrier safe)
#define TPB 384
#define WPB 12
#define NF4 (H / 4)
#define NWARPS (B1 * WPB) // 1776

__device__ float4 g_part[NF4][B1];
__device__ unsigned int g_cnt;   // monotone epoch counter (graph-replay safe)

__device__ __forceinline__ void load_row(float4 kv[8], const float* __restrict__ keys,
                                         int row, int lane) {
    const float4* k4 = (const float4*)(keys + (size_t)row * H);
#pragma unroll
    for (int j = 0; j < 8; j++) kv[j] = k4[lane + 32 * j];
}

__device__ __forceinline__ void process_row(const float4 kv[8], const float4* qs4,
                                            float qn_inv, int lane, float4 acc[8]) {
    float dot = 0.f, ss = 0.f;
#pragma unroll
    for (int j = 0; j < 8; j++) {
        float4 q = qs4[lane + 32 * j];
        dot += q.x * kv[j].x + q.y * kv[j].y + q.z * kv[j].z + q.w * kv[j].w;
        ss  += kv[j].x * kv[j].x + kv[j].y * kv[j].y
             + kv[j].z * kv[j].z + kv[j].w * kv[j].w;
    }
#pragma unroll
    for (int o = 16; o > 0; o >>= 1) {
        dot += __shfl_xor_sync(0xffffffffu, dot, o);
        ss  += __shfl_xor_sync(0xffffffffu, ss, o);
    }
    const float cosv = dot * qn_inv * rsqrtf(ss);
#pragma unroll
    for (int j = 0; j < 8; j++) {
        acc[j].x += cosv * kv[j].x;
        acc[j].y += cosv * kv[j].y;
        acc[j].z += cosv * kv[j].z;
        acc[j].w += cosv * kv[j].w;
    }
}

__global__ __launch_bounds__(TPB, 1)
void cosattn_fused(const float* __restrict__ query,
                   const float* __restrict__ keys,
                   float* __restrict__ out) {
    __shared__ float q_s[H];             // 4 KB
    __shared__ float warp_ctx[WPB][H];   // 48 KB

    const int tid  = threadIdx.x;
    const int wid  = tid >> 5;
    const int lane = tid & 31;
    const int gwarp = blockIdx.x * WPB + wid;   // < 1776

    for (int i = tid; i < NF4; i += TPB)
        ((float4*)q_s)[i] = ((const float4*)query)[i];
    __syncthreads();

    const float4* qs4 = (const float4*)q_s;
    float qss = 0.f;
#pragma unroll
    for (int j = 0; j < 8; j++) {
        float4 q = qs4[lane + 32 * j];
        qss += q.x * q.x + q.y * q.y + q.z * q.z + q.w * q.w;
    }
#pragma unroll
    for (int o = 16; o > 0; o >>= 1)
        qss += __shfl_xor_sync(0xffffffffu, qss, o);
    const float qn_inv = rsqrtf(qss);

    float4 acc[8];
#pragma unroll
    for (int j = 0; j < 8; j++) acc[j] = make_float4(0.f, 0.f, 0.f, 0.f);

    // ---- Double-buffered main loop: next row's LDGs issue before current butterfly ----
    float4 ka[8], kb[8];
    int next = gwarp + NWARPS;
    load_row(ka, keys, gwarp, lane);
    for (;;) {
        if (next < S) load_row(kb, keys, next, lane);
        process_row(ka, qs4, qn_inv, lane, acc);
        if (next >= S) break;
        next += NWARPS;

        if (next < S) load_row(ka, keys, next, lane);
        process_row(kb, qs4, qn_inv, lane, acc);
        if (next >= S) break;
        next += NWARPS;
    }

    // Block-level reduce via smem.
    float4* wctx4 = (float4*)warp_ctx[wid];
#pragma unroll
    for (int j = 0; j < 8; j++) wctx4[lane + 32 * j] = acc[j];
    __syncthreads();

    if (tid < NF4) {
        float4 sum = make_float4(0.f, 0.f, 0.f, 0.f);
#pragma unroll
        for (int w = 0; w < WPB; w++) {
            float4 v = ((const float4*)warp_ctx[w])[tid];
            sum.x += v.x; sum.y += v.y; sum.z += v.z; sum.w += v.w;
        }
        g_part[tid][blockIdx.x] = sum;
    }

    // ---- Grid barrier (148 co-resident blocks) ----
    __threadfence();
    __syncthreads();
    if (tid == 0) {
        unsigned int old = atomicAdd(&g_cnt, 1u);
        unsigned int target = old - (old % B1) + B1;
        while (*(volatile unsigned int*)&g_cnt < target)
            __nanosleep(64);
    }
    __syncthreads();
    __threadfence();

    // ---- Phase 2: blocks loop over float4 columns; warp-level final reduce ----
    // 148 values per column: warp w of 12 loads lane-strided, butterfly, lane0 writes.
    // Use one warp per column chunk: warp handles column c = blockIdx.x + (warp slot)*B1.
    {
        // Each of the 12 warps takes columns c = blockIdx.x + (wid + 12*k)*B1? NF4/B1 < 2,
        // so simply: warp 0 handles c0 = blockIdx.x, warp 1 handles c1 = blockIdx.x + B1 (if < NF4).
        const int c = blockIdx.x + wid * B1;
        if (c < NF4 && wid < 2) {
            float4 a = make_float4(0.f, 0.f, 0.f, 0.f);
            for (int r = lane; r < B1; r += 32) {   // ceil(148/32)=5 iters, coalesced
                float4 v = g_part[c][r];
                a.x += v.x; a.y += v.y; a.z += v.z; a.w += v.w;
            }
#pragma unroll
            for (int o = 16; o > 0; o >>= 1) {
                a.x += __shfl_xor_sync(0xffffffffu, a.x, o);
                a.y += __shfl_xor_sync(0xffffffffu, a.y, o);
                a.z += __shfl_xor_sync(0xffffffffu, a.z, o);
                a.w += __shfl_xor_sync(0xffffffffu, a.w, o);
            }
            if (lane == 0)
                ((float4*)out)[c] = a;
        }
    }
}

extern "C" void kernel_launch(void* const* d_in, const int* in_sizes, int n_in,
                              void* d_out, int out_size) {
    const float* query = (const float*)d_in[0];  // [1, 1024]
    const float* keys  = (const float*)d_in[1];  // [32768, 1024]
    float* out = (float*)d_out;                  // [1, 1024]

    cosattn_fused<<<B1, TPB>>>(query, keys, out);
}